// round 6
// baseline (speedup 1.0000x reference)
#include <cuda_runtime.h>
#include <math_constants.h>

// Problem shape (fixed by the reference): B=32, Q=512, K=512, D=1024.
// Inputs (metadata order): queries f32[B,Q,D], keys f32[B,K,D],
//                          temperature f32[], bias f32[]
// Output: attn f32[B,Q,K] followed by confidence f32[B,Q] in d_out.

#define BATCH 32
#define QDIM 512
#define KDIM 512
#define DDIM 1024

#define BM 128
#define BN 128
#define BK 16
#define LDS_STRIDE 132   // padded row stride (floats) to reduce STS bank conflicts

typedef unsigned long long ull;

__device__ __forceinline__ ull pack2(float lo, float hi) {
    ull r;
    asm("mov.b64 %0, {%1, %2};" : "=l"(r) : "f"(lo), "f"(hi));
    return r;
}
__device__ __forceinline__ void unpack2(ull v, float& lo, float& hi) {
    asm("mov.b64 {%0, %1}, %2;" : "=f"(lo), "=f"(hi) : "l"(v));
}
// d = a*b + d  (packed 2x fp32, Blackwell f32x2 pipe)
#define FMA2(d, a, b) \
    asm("fma.rn.f32x2 %0, %1, %2, %3;" : "=l"(d) : "l"(a), "l"(b), "l"(d))

// ---------------------------------------------------------------------------
// Kernel 1: batched NT GEMM  C[b,q,k] = sum_d Q[b,q,d] * K[b,k,d]
// with key-mask applied in epilogue (masked logits written as -inf).
// Tile 128x128, depth 16, 256 threads, 8x8 per-thread microtile computed as
// 4 M-pairs x 8 N via fma.rn.f32x2.
// ---------------------------------------------------------------------------
__global__ __launch_bounds__(256, 1)
void gemm_nt_mask_kernel(const float* __restrict__ Qg,
                         const float* __restrict__ Kg,
                         float* __restrict__ Cg) {
    const int bn = blockIdx.x * BN;            // key-tile base
    const int bm = blockIdx.y * BM;            // query-tile base
    const int b  = blockIdx.z;

    const float* A = Qg + (size_t)b * QDIM * DDIM;
    const float* Bp = Kg + (size_t)b * KDIM * DDIM;
    float* C = Cg + (size_t)b * QDIM * KDIM;

    __shared__ float As[BK][LDS_STRIDE];
    __shared__ float Bs[BK][LDS_STRIDE];
    __shared__ float maskv[BN];                // 1.0 if key col masked

    const int tid = threadIdx.x;

    // Key mask for this tile's 128 columns: keys[b][bn+j][0] == 0
    if (tid < BN) {
        float k0 = Bp[(size_t)(bn + tid) * DDIM];
        maskv[tid] = (k0 == 0.0f) ? 1.0f : 0.0f;
    }

    // ---- global loader mapping: each thread loads 2 float4 per operand tile
    const int ld_row = tid >> 2;               // 0..63
    const int ld_col = (tid & 3) * 4;          // 0,4,8,12 (k within tile)

    // ---- compute mapping: 8 warps as 4(M) x 2(N); warp tile 32x64;
    //      lane as 4(M) x 8(N); thread tile 8x8.
    const int warp = tid >> 5;
    const int lane = tid & 31;
    const int m0 = (warp >> 1) * 32 + (lane >> 3) * 8;   // row base in tile
    const int n0 = (warp & 1) * 64 + (lane & 7) * 8;     // col base in tile

    ull acc[4][8];
    #pragma unroll
    for (int i = 0; i < 4; ++i)
        #pragma unroll
        for (int j = 0; j < 8; ++j) acc[i][j] = pack2(0.0f, 0.0f);

    const float* pa0 = A  + (size_t)(bm + ld_row)      * DDIM + ld_col;
    const float* pa1 = A  + (size_t)(bm + ld_row + 64) * DDIM + ld_col;
    const float* pb0 = Bp + (size_t)(bn + ld_row)      * DDIM + ld_col;
    const float* pb1 = Bp + (size_t)(bn + ld_row + 64) * DDIM + ld_col;

    float4 ra0 = *(const float4*)pa0;
    float4 ra1 = *(const float4*)pa1;
    float4 rb0 = *(const float4*)pb0;
    float4 rb1 = *(const float4*)pb1;

    const int NT = DDIM / BK;                  // 64 k-tiles
    for (int t = 0; t < NT; ++t) {
        __syncthreads();                       // previous tile's compute done
        {   // transpose-store the prefetched registers into smem
            const float* a0 = &ra0.x; const float* a1 = &ra1.x;
            const float* b0 = &rb0.x; const float* b1 = &rb1.x;
            #pragma unroll
            for (int j = 0; j < 4; ++j) {
                As[ld_col + j][ld_row]      = a0[j];
                As[ld_col + j][ld_row + 64] = a1[j];
                Bs[ld_col + j][ld_row]      = b0[j];
                Bs[ld_col + j][ld_row + 64] = b1[j];
            }
        }
        __syncthreads();

        if (t < NT - 1) {                      // prefetch next k-tile
            pa0 += BK; pa1 += BK; pb0 += BK; pb1 += BK;
            ra0 = *(const float4*)pa0;
            ra1 = *(const float4*)pa1;
            rb0 = *(const float4*)pb0;
            rb1 = *(const float4*)pb1;
        }

        #pragma unroll
        for (int k = 0; k < BK; ++k) {
            // A fragment: 8 consecutive rows -> 4 packed f32x2 pairs, no mov
            const ull* ap = reinterpret_cast<const ull*>(&As[k][m0]);
            ull a0 = ap[0], a1 = ap[1], a2 = ap[2], a3 = ap[3];
            // B fragment: 8 values, duplicated into both lanes
            float4 blo = *(const float4*)&Bs[k][n0];
            float4 bhi = *(const float4*)&Bs[k][n0 + 4];
            ull bb0 = pack2(blo.x, blo.x), bb1 = pack2(blo.y, blo.y);
            ull bb2 = pack2(blo.z, blo.z), bb3 = pack2(blo.w, blo.w);
            ull bb4 = pack2(bhi.x, bhi.x), bb5 = pack2(bhi.y, bhi.y);
            ull bb6 = pack2(bhi.z, bhi.z), bb7 = pack2(bhi.w, bhi.w);

            FMA2(acc[0][0], a0, bb0); FMA2(acc[0][1], a0, bb1);
            FMA2(acc[0][2], a0, bb2); FMA2(acc[0][3], a0, bb3);
            FMA2(acc[0][4], a0, bb4); FMA2(acc[0][5], a0, bb5);
            FMA2(acc[0][6], a0, bb6); FMA2(acc[0][7], a0, bb7);

            FMA2(acc[1][0], a1, bb0); FMA2(acc[1][1], a1, bb1);
            FMA2(acc[1][2], a1, bb2); FMA2(acc[1][3], a1, bb3);
            FMA2(acc[1][4], a1, bb4); FMA2(acc[1][5], a1, bb5);
            FMA2(acc[1][6], a1, bb6); FMA2(acc[1][7], a1, bb7);

            FMA2(acc[2][0], a2, bb0); FMA2(acc[2][1], a2, bb1);
            FMA2(acc[2][2], a2, bb2); FMA2(acc[2][3], a2, bb3);
            FMA2(acc[2][4], a2, bb4); FMA2(acc[2][5], a2, bb5);
            FMA2(acc[2][6], a2, bb6); FMA2(acc[2][7], a2, bb7);

            FMA2(acc[3][0], a3, bb0); FMA2(acc[3][1], a3, bb1);
            FMA2(acc[3][2], a3, bb2); FMA2(acc[3][3], a3, bb3);
            FMA2(acc[3][4], a3, bb4); FMA2(acc[3][5], a3, bb5);
            FMA2(acc[3][6], a3, bb6); FMA2(acc[3][7], a3, bb7);
        }
    }

    // ---- epilogue: unpack, apply key mask, write float4s
    float msk[8];
    #pragma unroll
    for (int j = 0; j < 8; ++j) msk[j] = maskv[n0 + j];

    #pragma unroll
    for (int i = 0; i < 4; ++i) {
        float r0v[8], r1v[8];
        #pragma unroll
        for (int j = 0; j < 8; ++j) {
            float lo, hi;
            unpack2(acc[i][j], lo, hi);
            if (msk[j] != 0.0f) { lo = -CUDART_INF_F; hi = -CUDART_INF_F; }
            r0v[j] = lo; r1v[j] = hi;
        }
        const int gr0 = bm + m0 + 2 * i;       // even row of the pair
        const int gc  = bn + n0;
        float4* o0 = (float4*)&C[(size_t)gr0 * KDIM + gc];
        float4* o1 = (float4*)&C[(size_t)(gr0 + 1) * KDIM + gc];
        o0[0] = make_float4(r0v[0], r0v[1], r0v[2], r0v[3]);
        o0[1] = make_float4(r0v[4], r0v[5], r0v[6], r0v[7]);
        o1[0] = make_float4(r1v[0], r1v[1], r1v[2], r1v[3]);
        o1[1] = make_float4(r1v[4], r1v[5], r1v[6], r1v[7]);
    }
}

// ---------------------------------------------------------------------------
// Kernel 2: per-row masked softmax (in place over logits) + confidence.
// One 128-thread block per (b,q) row; 4 elements (one float4) per thread.
// confidence[b,q] = sigmoid((max + log(sum_exp) + bias) * temperature)
// ---------------------------------------------------------------------------
__global__ __launch_bounds__(128)
void softmax_conf_kernel(const float* __restrict__ tptr,
                         const float* __restrict__ bptr,
                         float* __restrict__ out) {
    __shared__ float red[4];
    const int row = blockIdx.x;                // b*Q + q
    float* lr = out + (size_t)row * KDIM;
    const int tid = threadIdx.x;

    float4 v = *(const float4*)(lr + tid * 4);

    // --- max reduce
    float m = fmaxf(fmaxf(v.x, v.y), fmaxf(v.z, v.w));
    #pragma unroll
    for (int o = 16; o > 0; o >>= 1)
        m = fmaxf(m, __shfl_xor_sync(0xffffffffu, m, o));
    if ((tid & 31) == 0) red[tid >> 5] = m;
    __syncthreads();
    m = fmaxf(fmaxf(red[0], red[1]), fmaxf(red[2], red[3]));
    __syncthreads();                           // red reused below

    // --- exp + sum reduce  (exp(-inf - m) = 0 handles masked cols)
    float e0 = __expf(v.x - m);
    float e1 = __expf(v.y - m);
    float e2 = __expf(v.z - m);
    float e3 = __expf(v.w - m);
    float s = (e0 + e1) + (e2 + e3);
    #pragma unroll
    for (int o = 16; o > 0; o >>= 1)
        s += __shfl_xor_sync(0xffffffffu, s, o);
    if ((tid & 31) == 0) red[tid >> 5] = s;
    __syncthreads();
    s = (red[0] + red[1]) + (red[2] + red[3]);

    const float inv = 1.0f / s;
    float4 o4 = make_float4(e0 * inv, e1 * inv, e2 * inv, e3 * inv);
    *(float4*)(lr + tid * 4) = o4;

    if (tid == 0) {
        const float lse = m + logf(s);
        const float x = (lse + bptr[0]) * tptr[0];
        const float conf = 1.0f / (1.0f + __expf(-x));
        out[(size_t)BATCH * QDIM * KDIM + row] = conf;
    }
}

// ---------------------------------------------------------------------------
extern "C" void kernel_launch(void* const* d_in, const int* in_sizes, int n_in,
                              void* d_out, int out_size) {
    const float* q    = (const float*)d_in[0];
    const float* k    = (const float*)d_in[1];
    const float* temp = (const float*)d_in[2];
    const float* bias = (const float*)d_in[3];
    float* out = (float*)d_out;

    dim3 ggrid(KDIM / BN, QDIM / BM, BATCH);   // (4, 4, 32) = 512 CTAs
    gemm_nt_mask_kernel<<<ggrid, 256>>>(q, k, out);

    softmax_conf_kernel<<<BATCH * QDIM, 128>>>(temp, bias, out);
}

// round 8
// speedup vs baseline: 2.0102x; 2.0102x over previous
#include <cuda_runtime.h>
#include <cuda_bf16.h>
#include <cstdint>

// Problem shape (fixed): B=32, Q=512, K=512, D=1024, fp32.
// Inputs: queries f32[B,Q,D], keys f32[B,K,D], temperature f32[], bias f32[]
// Output: attn f32[B,Q,K] then confidence f32[B,Q].
//
// NOTE: tcgen05/TMEM is NOT usable — the bench pipeline targets plain sm_103
// PTX (no 'a' suffix), which rejects arch-specific instructions. This kernel
// uses only sm_80-era standard PTX: ldmatrix + mma.sync (HMMA tensor path).

#define BATCH 32
#define QDIM 512
#define KDIM 512
#define DDIM 1024

#define TM 128
#define TN 128
#define CK 16                    // k floats per stage
#define NST (DDIM / CK)          // 64 stages

// ---------------- PTX helpers ----------------
__device__ __forceinline__ uint32_t smem_u32(const void* p) {
    uint32_t a;
    asm("{ .reg .u64 t; cvta.to.shared.u64 t, %1; cvt.u32.u64 %0, t; }"
        : "=r"(a) : "l"(p));
    return a;
}

#define LDSM4(r0, r1, r2, r3, addr)                                        \
    asm volatile("ldmatrix.sync.aligned.m8n8.x4.shared.b16 "               \
                 "{%0, %1, %2, %3}, [%4];"                                 \
                 : "=r"(r0), "=r"(r1), "=r"(r2), "=r"(r3) : "r"(addr))

#define STS128(addr, r0, r1, r2, r3)                                       \
    asm volatile("st.shared.v4.b32 [%0], {%1, %2, %3, %4};"                \
                 :: "r"(addr), "r"(r0), "r"(r1), "r"(r2), "r"(r3) : "memory")

#define MMA16816(c, a0, a1, a2, a3, b0, b1)                                \
    asm volatile("mma.sync.aligned.m16n8k16.row.col.f32.bf16.bf16.f32 "    \
                 "{%0, %1, %2, %3}, {%4, %5, %6, %7}, {%8, %9}, "          \
                 "{%0, %1, %2, %3};"                                       \
                 : "+f"((c)[0]), "+f"((c)[1]), "+f"((c)[2]), "+f"((c)[3])  \
                 : "r"(a0), "r"(a1), "r"(a2), "r"(a3), "r"(b0), "r"(b1))

// Split (x, y) into bf16 hi pair and bf16 lo pair (packed 2x16-bit words).
// hi = rn_bf16(x); lo = rn_bf16(x - hi).  x is represented to ~2^-18 rel.
__device__ __forceinline__ void split2(float x, float y,
                                       uint32_t& h, uint32_t& l) {
    __nv_bfloat162 hh = __floats2bfloat162_rn(x, y);
    float rx = x - __bfloat162float(hh.x);
    float ry = y - __bfloat162float(hh.y);
    __nv_bfloat162 ll = __floats2bfloat162_rn(rx, ry);
    h = reinterpret_cast<uint32_t&>(hh);
    l = reinterpret_cast<uint32_t&>(ll);
}

// Swizzled byte offset for element row r, 16-byte chunk c (c = kcol>>3) in a
// [128 x 16] bf16 tile with 32B rows. The XOR on (r>>2)&1 makes every
// 8-row x 16B ldmatrix phase and every STS wavefront bank-conflict-free.
__device__ __forceinline__ uint32_t swz(int r, int c) {
    return (uint32_t)(r * 32 + ((c ^ ((r >> 2) & 1)) << 4));
}

// ---------------------------------------------------------------------------
// GEMM: logits[b,q,k] = sum_d Q*K via 4x bf16 mma.sync split; mask -> -inf
// CTA 128x128, 256 threads, warps 4(M) x 2(N), warp tile 32x64.
// ---------------------------------------------------------------------------
__global__ __launch_bounds__(256, 2)
void gemm_bf16split_kernel(const float* __restrict__ Qg,
                           const float* __restrict__ Kg,
                           float* __restrict__ Cg) {
    __shared__ __align__(128) uint8_t sAh[4096], sAl[4096];
    __shared__ __align__(128) uint8_t sBh[4096], sBl[4096];
    __shared__ float maskv[TN];

    const int tid  = threadIdx.x;
    const int lane = tid & 31;
    const int wid  = tid >> 5;
    const int wm   = wid & 3;          // 0..3  (M)
    const int wn   = wid >> 2;         // 0..1  (N)

    const int bn = blockIdx.x * TN;
    const int bm = blockIdx.y * TM;
    const int b  = blockIdx.z;

    const float* A  = Qg + (size_t)b * QDIM * DDIM;
    const float* Bp = Kg + (size_t)b * KDIM * DDIM;
    float*       C  = Cg + (size_t)b * QDIM * KDIM;

    if (tid < TN)
        maskv[tid] = (Bp[(size_t)(bn + tid) * DDIM] == 0.0f) ? 1.0f : 0.0f;

    // ---- producer mapping: thread -> (row, k-half); 8 floats per operand ----
    const int pr = tid >> 1;           // 0..127
    const int ph = tid & 1;            // chunk (k 0-7 or 8-15)
    const uint32_t so = swz(pr, ph);
    const uint32_t stAh = smem_u32(sAh) + so;
    const uint32_t stAl = smem_u32(sAl) + so;
    const uint32_t stBh = smem_u32(sBh) + so;
    const uint32_t stBl = smem_u32(sBl) + so;
    const float* gA = A  + (size_t)(bm + pr) * DDIM + ph * 8;
    const float* gB = Bp + (size_t)(bn + pr) * DDIM + ph * 8;

    // ---- ldmatrix addresses (loop-invariant; single smem buffer) ----
    // A x4: lanes 0-7 rows m+0..7 chk0 | 8-15 rows m+8..15 chk0
    //       | 16-23 rows m+0..7 chk1 | 24-31 rows m+8..15 chk1
    uint32_t lmA, lmB;
    {
        int r = wm * 32 + (lane & 15);
        int c = lane >> 4;
        lmA = swz(r, c);
    }
    // B x4: lanes 0-7 n+0..7 chk0 | 8-15 n+0..7 chk1
    //       | 16-23 n+8..15 chk0 | 24-31 n+8..15 chk1
    {
        int r = wn * 64 + (lane & 7) + ((lane >> 4) << 3);
        int c = (lane >> 3) & 1;
        lmB = swz(r, c);
    }
    const uint32_t aAh = smem_u32(sAh) + lmA;
    const uint32_t aAl = smem_u32(sAl) + lmA;
    const uint32_t aBh = smem_u32(sBh) + lmB;
    const uint32_t aBl = smem_u32(sBl) + lmB;

    float acc[2][8][4];
    #pragma unroll
    for (int i = 0; i < 2; ++i)
        #pragma unroll
        for (int j = 0; j < 8; ++j)
            #pragma unroll
            for (int k = 0; k < 4; ++k) acc[i][j][k] = 0.0f;

    // ---- prologue: load stage 0 ----
    float4 va0 = *(const float4*)gA;
    float4 va1 = *(const float4*)(gA + 4);
    float4 vb0 = *(const float4*)gB;
    float4 vb1 = *(const float4*)(gB + 4);

    for (int s = 0; s < NST; ++s) {
        __syncthreads();               // previous stage's ldmatrix done

        // ---- split + store current stage ----
        {
            uint32_t h0, h1, h2, h3, l0, l1, l2, l3;
            split2(va0.x, va0.y, h0, l0); split2(va0.z, va0.w, h1, l1);
            split2(va1.x, va1.y, h2, l2); split2(va1.z, va1.w, h3, l3);
            STS128(stAh, h0, h1, h2, h3);
            STS128(stAl, l0, l1, l2, l3);
            split2(vb0.x, vb0.y, h0, l0); split2(vb0.z, vb0.w, h1, l1);
            split2(vb1.x, vb1.y, h2, l2); split2(vb1.z, vb1.w, h3, l3);
            STS128(stBh, h0, h1, h2, h3);
            STS128(stBl, l0, l1, l2, l3);
        }
        __syncthreads();

        // ---- prefetch next stage (overlaps with compute below) ----
        if (s + 1 < NST) {
            gA += CK; gB += CK;
            va0 = *(const float4*)gA;
            va1 = *(const float4*)(gA + 4);
            vb0 = *(const float4*)gB;
            vb1 = *(const float4*)(gB + 4);
        }

        // ---- compute: 12 ldmatrix.x4 + 64 HMMA per warp ----
        uint32_t Ah[2][4], Al[2][4];
        LDSM4(Ah[0][0], Ah[0][1], Ah[0][2], Ah[0][3], aAh);
        LDSM4(Ah[1][0], Ah[1][1], Ah[1][2], Ah[1][3], aAh + 512);
        LDSM4(Al[0][0], Al[0][1], Al[0][2], Al[0][3], aAl);
        LDSM4(Al[1][0], Al[1][1], Al[1][2], Al[1][3], aAl + 512);

        #pragma unroll
        for (int q = 0; q < 4; ++q) {          // 16 n-rows per quad
            uint32_t Bh[4], Bl[4];
            LDSM4(Bh[0], Bh[1], Bh[2], Bh[3], aBh + q * 512);
            LDSM4(Bl[0], Bl[1], Bl[2], Bl[3], aBl + q * 512);
            #pragma unroll
            for (int mi = 0; mi < 2; ++mi) {
                float* c0 = acc[mi][2 * q];
                float* c1 = acc[mi][2 * q + 1];
                MMA16816(c0, Ah[mi][0], Ah[mi][1], Ah[mi][2], Ah[mi][3], Bh[0], Bh[1]);
                MMA16816(c0, Ah[mi][0], Ah[mi][1], Ah[mi][2], Ah[mi][3], Bl[0], Bl[1]);
                MMA16816(c0, Al[mi][0], Al[mi][1], Al[mi][2], Al[mi][3], Bh[0], Bh[1]);
                MMA16816(c0, Al[mi][0], Al[mi][1], Al[mi][2], Al[mi][3], Bl[0], Bl[1]);
                MMA16816(c1, Ah[mi][0], Ah[mi][1], Ah[mi][2], Ah[mi][3], Bh[2], Bh[3]);
                MMA16816(c1, Ah[mi][0], Ah[mi][1], Ah[mi][2], Ah[mi][3], Bl[2], Bl[3]);
                MMA16816(c1, Al[mi][0], Al[mi][1], Al[mi][2], Al[mi][3], Bh[2], Bh[3]);
                MMA16816(c1, Al[mi][0], Al[mi][1], Al[mi][2], Al[mi][3], Bl[2], Bl[3]);
            }
        }
    }

    // ---- epilogue: apply key mask, write C ----
    const float NEG_INF = __int_as_float(0xff800000);
    const int mrow  = bm + wm * 32 + (lane >> 2);
    const int ncl   = wn * 64 + (lane & 3) * 2;      // local col base
    #pragma unroll
    for (int mi = 0; mi < 2; ++mi) {
        #pragma unroll
        for (int ni = 0; ni < 8; ++ni) {
            const int nc = ncl + ni * 8;
            const float m0 = maskv[nc];
            const float m1 = maskv[nc + 1];
            const float* c = acc[mi][ni];
            float2 v0, v1;
            v0.x = (m0 != 0.0f) ? NEG_INF : c[0];
            v0.y = (m1 != 0.0f) ? NEG_INF : c[1];
            v1.x = (m0 != 0.0f) ? NEG_INF : c[2];
            v1.y = (m1 != 0.0f) ? NEG_INF : c[3];
            float* base = C + (size_t)(mrow + mi * 16) * KDIM + bn + nc;
            *(float2*)base               = v0;
            *(float2*)(base + 8 * KDIM)  = v1;
        }
    }
}

// ---------------------------------------------------------------------------
// Softmax + confidence (memory-floor at ~14us)
// ---------------------------------------------------------------------------
__global__ __launch_bounds__(128)
void softmax_conf_kernel(const float* __restrict__ tptr,
                         const float* __restrict__ bptr,
                         float* __restrict__ out) {
    __shared__ float red[4];
    const int row = blockIdx.x;
    float* lr = out + (size_t)row * KDIM;
    const int tid = threadIdx.x;

    float4 v = *(const float4*)(lr + tid * 4);

    float m = fmaxf(fmaxf(v.x, v.y), fmaxf(v.z, v.w));
    #pragma unroll
    for (int o = 16; o > 0; o >>= 1)
        m = fmaxf(m, __shfl_xor_sync(0xffffffffu, m, o));
    if ((tid & 31) == 0) red[tid >> 5] = m;
    __syncthreads();
    m = fmaxf(fmaxf(red[0], red[1]), fmaxf(red[2], red[3]));
    __syncthreads();

    float e0 = __expf(v.x - m);
    float e1 = __expf(v.y - m);
    float e2 = __expf(v.z - m);
    float e3 = __expf(v.w - m);
    float s = (e0 + e1) + (e2 + e3);
    #pragma unroll
    for (int o = 16; o > 0; o >>= 1)
        s += __shfl_xor_sync(0xffffffffu, s, o);
    if ((tid & 31) == 0) red[tid >> 5] = s;
    __syncthreads();
    s = (red[0] + red[1]) + (red[2] + red[3]);

    const float inv = 1.0f / s;
    *(float4*)(lr + tid * 4) = make_float4(e0 * inv, e1 * inv, e2 * inv, e3 * inv);

    if (tid == 0) {
        const float lse = m + logf(s);
        const float x = (lse + bptr[0]) * tptr[0];
        out[(size_t)BATCH * QDIM * KDIM + row] = 1.0f / (1.0f + __expf(-x));
    }
}

// ---------------------------------------------------------------------------
extern "C" void kernel_launch(void* const* d_in, const int* in_sizes, int n_in,
                              void* d_out, int out_size) {
    const float* q    = (const float*)d_in[0];
    const float* k    = (const float*)d_in[1];
    const float* temp = (const float*)d_in[2];
    const float* bias = (const float*)d_in[3];
    float* out = (float*)d_out;

    dim3 ggrid(KDIM / TN, QDIM / TM, BATCH);   // (4, 4, 32) = 512 CTAs
    gemm_bf16split_kernel<<<ggrid, 256>>>(q, k, out);

    softmax_conf_kernel<<<BATCH * QDIM, 128>>>(temp, bias, out);
}

// round 9
// speedup vs baseline: 2.3268x; 1.1575x over previous
#include <cuda_runtime.h>
#include <cuda_bf16.h>
#include <cstdint>

// Problem shape (fixed): B=32, Q=512, K=512, D=1024, fp32.
// Inputs: queries f32[B,Q,D], keys f32[B,K,D], temperature f32[], bias f32[]
// Output: attn f32[B,Q,K] then confidence f32[B,Q].
//
// tcgen05/TMEM unusable (bench targets plain sm_103 PTX). Tensor path is
// sm_80-era ldmatrix + mma.sync (HMMA). Error-free bf16 2-term split,
// 3 MMA products (hi*hi + hi*lo + lo*hi; lo*lo dropped, ~2e-4 attn rel err).

#define BATCH 32
#define QDIM 512
#define KDIM 512
#define DDIM 1024

#define TM 128
#define TN 128
#define CK 16                    // k floats per stage
#define NST (DDIM / CK)          // 64 stages

// ---------------- PTX helpers ----------------
__device__ __forceinline__ uint32_t smem_u32(const void* p) {
    uint32_t a;
    asm("{ .reg .u64 t; cvta.to.shared.u64 t, %1; cvt.u32.u64 %0, t; }"
        : "=r"(a) : "l"(p));
    return a;
}

#define LDSM4(r0, r1, r2, r3, addr)                                        \
    asm volatile("ldmatrix.sync.aligned.m8n8.x4.shared.b16 "               \
                 "{%0, %1, %2, %3}, [%4];"                                 \
                 : "=r"(r0), "=r"(r1), "=r"(r2), "=r"(r3) : "r"(addr))

#define STS128(addr, r0, r1, r2, r3)                                       \
    asm volatile("st.shared.v4.b32 [%0], {%1, %2, %3, %4};"                \
                 :: "r"(addr), "r"(r0), "r"(r1), "r"(r2), "r"(r3) : "memory")

#define MMA16816(c, a0, a1, a2, a3, b0, b1)                                \
    asm volatile("mma.sync.aligned.m16n8k16.row.col.f32.bf16.bf16.f32 "    \
                 "{%0, %1, %2, %3}, {%4, %5, %6, %7}, {%8, %9}, "          \
                 "{%0, %1, %2, %3};"                                       \
                 : "+f"((c)[0]), "+f"((c)[1]), "+f"((c)[2]), "+f"((c)[3])  \
                 : "r"(a0), "r"(a1), "r"(a2), "r"(a3), "r"(b0), "r"(b1))

// Split (x, y) into bf16 hi pair and bf16 lo pair (packed 2x16-bit words).
__device__ __forceinline__ void split2(float x, float y,
                                       uint32_t& h, uint32_t& l) {
    __nv_bfloat162 hh = __floats2bfloat162_rn(x, y);
    float rx = x - __bfloat162float(hh.x);
    float ry = y - __bfloat162float(hh.y);
    __nv_bfloat162 ll = __floats2bfloat162_rn(rx, ry);
    h = reinterpret_cast<uint32_t&>(hh);
    l = reinterpret_cast<uint32_t&>(ll);
}

// Swizzled byte offset for row r, 16-byte chunk c in a [128 x 16] bf16 tile
// (32B rows). XOR keeps ldmatrix phases and STS wavefronts conflict-free.
__device__ __forceinline__ uint32_t swz(int r, int c) {
    return (uint32_t)(r * 32 + ((c ^ ((r >> 2) & 1)) << 4));
}

// ---------------------------------------------------------------------------
// GEMM: logits = Q*K^T via 3x bf16 mma.sync split; key mask -> -inf.
// CTA 128x128, 256 threads, warps 4(M) x 2(N); double-buffered smem,
// one barrier per stage.
// ---------------------------------------------------------------------------
__global__ __launch_bounds__(256, 2)
void gemm_bf16split_kernel(const float* __restrict__ Qg,
                           const float* __restrict__ Kg,
                           float* __restrict__ Cg) {
    __shared__ __align__(128) uint8_t sAh[2][4096], sAl[2][4096];
    __shared__ __align__(128) uint8_t sBh[2][4096], sBl[2][4096];
    __shared__ float maskv[TN];

    const int tid  = threadIdx.x;
    const int lane = tid & 31;
    const int wid  = tid >> 5;
    const int wm   = wid & 3;          // 0..3  (M)
    const int wn   = wid >> 2;         // 0..1  (N)

    const int bn = blockIdx.x * TN;
    const int bm = blockIdx.y * TM;
    const int b  = blockIdx.z;

    const float* A  = Qg + (size_t)b * QDIM * DDIM;
    const float* Bp = Kg + (size_t)b * KDIM * DDIM;
    float*       C  = Cg + (size_t)b * QDIM * KDIM;

    if (tid < TN)
        maskv[tid] = (Bp[(size_t)(bn + tid) * DDIM] == 0.0f) ? 1.0f : 0.0f;

    // ---- producer mapping: thread -> (row, k-half); 8 floats per operand ----
    const int pr = tid >> 1;           // 0..127
    const int ph = tid & 1;            // 16B chunk (k 0-7 / 8-15)
    const uint32_t so = swz(pr, ph);
    const uint32_t stAh = smem_u32(sAh) + so;
    const uint32_t stAl = smem_u32(sAl) + so;
    const uint32_t stBh = smem_u32(sBh) + so;
    const uint32_t stBl = smem_u32(sBl) + so;
    const float* gA = A  + (size_t)(bm + pr) * DDIM + ph * 8;
    const float* gB = Bp + (size_t)(bn + pr) * DDIM + ph * 8;

    // ---- ldmatrix addresses (buffer 0 base; +4096 selects buffer 1) ----
    uint32_t lmA, lmB;
    {
        int r = wm * 32 + (lane & 15);
        int c = lane >> 4;
        lmA = swz(r, c);
    }
    {
        int r = wn * 64 + (lane & 7) + ((lane >> 4) << 3);
        int c = (lane >> 3) & 1;
        lmB = swz(r, c);
    }
    const uint32_t aAh = smem_u32(sAh) + lmA;
    const uint32_t aAl = smem_u32(sAl) + lmA;
    const uint32_t aBh = smem_u32(sBh) + lmB;
    const uint32_t aBl = smem_u32(sBl) + lmB;

    float acc[2][8][4];
    #pragma unroll
    for (int i = 0; i < 2; ++i)
        #pragma unroll
        for (int j = 0; j < 8; ++j)
            #pragma unroll
            for (int k = 0; k < 4; ++k) acc[i][j][k] = 0.0f;

    // ---- prologue: stage 0 -> buf0, prefetch stage 1 into registers ----
    float4 va0 = *(const float4*)gA;
    float4 va1 = *(const float4*)(gA + 4);
    float4 vb0 = *(const float4*)gB;
    float4 vb1 = *(const float4*)(gB + 4);
    {
        uint32_t h0, h1, h2, h3, l0, l1, l2, l3;
        split2(va0.x, va0.y, h0, l0); split2(va0.z, va0.w, h1, l1);
        split2(va1.x, va1.y, h2, l2); split2(va1.z, va1.w, h3, l3);
        STS128(stAh, h0, h1, h2, h3);
        STS128(stAl, l0, l1, l2, l3);
        split2(vb0.x, vb0.y, h0, l0); split2(vb0.z, vb0.w, h1, l1);
        split2(vb1.x, vb1.y, h2, l2); split2(vb1.z, vb1.w, h3, l3);
        STS128(stBh, h0, h1, h2, h3);
        STS128(stBl, l0, l1, l2, l3);
    }
    gA += CK; gB += CK;
    va0 = *(const float4*)gA;
    va1 = *(const float4*)(gA + 4);
    vb0 = *(const float4*)gB;
    vb1 = *(const float4*)(gB + 4);
    __syncthreads();

    for (int s = 0; s < NST; ++s) {
        const uint32_t rd = (uint32_t)(s & 1) * 4096;
        const uint32_t wr = 4096 - rd;

        // ---- A fragments from the read buffer ----
        uint32_t Ah[2][4], Al[2][4];
        LDSM4(Ah[0][0], Ah[0][1], Ah[0][2], Ah[0][3], aAh + rd);
        LDSM4(Ah[1][0], Ah[1][1], Ah[1][2], Ah[1][3], aAh + rd + 512);
        LDSM4(Al[0][0], Al[0][1], Al[0][2], Al[0][3], aAl + rd);
        LDSM4(Al[1][0], Al[1][1], Al[1][2], Al[1][3], aAl + rd + 512);

        // ---- split + store NEXT stage into the write buffer (overlaps) ----
        if (s + 1 < NST) {
            uint32_t h0, h1, h2, h3, l0, l1, l2, l3;
            split2(va0.x, va0.y, h0, l0); split2(va0.z, va0.w, h1, l1);
            split2(va1.x, va1.y, h2, l2); split2(va1.z, va1.w, h3, l3);
            STS128(stAh + wr, h0, h1, h2, h3);
            STS128(stAl + wr, l0, l1, l2, l3);
            split2(vb0.x, vb0.y, h0, l0); split2(vb0.z, vb0.w, h1, l1);
            split2(vb1.x, vb1.y, h2, l2); split2(vb1.z, vb1.w, h3, l3);
            STS128(stBh + wr, h0, h1, h2, h3);
            STS128(stBl + wr, l0, l1, l2, l3);
        }
        // ---- prefetch stage s+2 from gmem ----
        if (s + 2 < NST) {
            gA += CK; gB += CK;
            va0 = *(const float4*)gA;
            va1 = *(const float4*)(gA + 4);
            vb0 = *(const float4*)gB;
            vb1 = *(const float4*)(gB + 4);
        }

        // ---- 8 B-LDSM + 48 HMMA (3 products) ----
        #pragma unroll
        for (int q = 0; q < 4; ++q) {
            uint32_t Bh[4], Bl[4];
            LDSM4(Bh[0], Bh[1], Bh[2], Bh[3], aBh + rd + q * 512);
            LDSM4(Bl[0], Bl[1], Bl[2], Bl[3], aBl + rd + q * 512);
            #pragma unroll
            for (int mi = 0; mi < 2; ++mi) {
                float* c0 = acc[mi][2 * q];
                float* c1 = acc[mi][2 * q + 1];
                MMA16816(c0, Ah[mi][0], Ah[mi][1], Ah[mi][2], Ah[mi][3], Bh[0], Bh[1]);
                MMA16816(c0, Ah[mi][0], Ah[mi][1], Ah[mi][2], Ah[mi][3], Bl[0], Bl[1]);
                MMA16816(c0, Al[mi][0], Al[mi][1], Al[mi][2], Al[mi][3], Bh[0], Bh[1]);
                MMA16816(c1, Ah[mi][0], Ah[mi][1], Ah[mi][2], Ah[mi][3], Bh[2], Bh[3]);
                MMA16816(c1, Ah[mi][0], Ah[mi][1], Ah[mi][2], Ah[mi][3], Bl[2], Bl[3]);
                MMA16816(c1, Al[mi][0], Al[mi][1], Al[mi][2], Al[mi][3], Bh[2], Bh[3]);
            }
        }
        __syncthreads();
    }

    // ---- epilogue: apply key mask, write C ----
    const float NEG_INF = __int_as_float(0xff800000);
    const int mrow = bm + wm * 32 + (lane >> 2);
    const int ncl  = wn * 64 + (lane & 3) * 2;
    #pragma unroll
    for (int mi = 0; mi < 2; ++mi) {
        #pragma unroll
        for (int ni = 0; ni < 8; ++ni) {
            const int nc = ncl + ni * 8;
            const float m0 = maskv[nc];
            const float m1 = maskv[nc + 1];
            const float* c = acc[mi][ni];
            float2 v0, v1;
            v0.x = (m0 != 0.0f) ? NEG_INF : c[0];
            v0.y = (m1 != 0.0f) ? NEG_INF : c[1];
            v1.x = (m0 != 0.0f) ? NEG_INF : c[2];
            v1.y = (m1 != 0.0f) ? NEG_INF : c[3];
            float* base = C + (size_t)(mrow + mi * 16) * KDIM + bn + nc;
            *(float2*)base              = v0;
            *(float2*)(base + 8 * KDIM) = v1;
        }
    }
}

// ---------------------------------------------------------------------------
// Softmax + confidence
// ---------------------------------------------------------------------------
__global__ __launch_bounds__(128)
void softmax_conf_kernel(const float* __restrict__ tptr,
                         const float* __restrict__ bptr,
                         float* __restrict__ out) {
    __shared__ float red[4];
    const int row = blockIdx.x;
    float* lr = out + (size_t)row * KDIM;
    const int tid = threadIdx.x;

    float4 v = *(const float4*)(lr + tid * 4);

    float m = fmaxf(fmaxf(v.x, v.y), fmaxf(v.z, v.w));
    #pragma unroll
    for (int o = 16; o > 0; o >>= 1)
        m = fmaxf(m, __shfl_xor_sync(0xffffffffu, m, o));
    if ((tid & 31) == 0) red[tid >> 5] = m;
    __syncthreads();
    m = fmaxf(fmaxf(red[0], red[1]), fmaxf(red[2], red[3]));
    __syncthreads();

    float e0 = __expf(v.x - m);
    float e1 = __expf(v.y - m);
    float e2 = __expf(v.z - m);
    float e3 = __expf(v.w - m);
    float s = (e0 + e1) + (e2 + e3);
    #pragma unroll
    for (int o = 16; o > 0; o >>= 1)
        s += __shfl_xor_sync(0xffffffffu, s, o);
    if ((tid & 31) == 0) red[tid >> 5] = s;
    __syncthreads();
    s = (red[0] + red[1]) + (red[2] + red[3]);

    const float inv = 1.0f / s;
    *(float4*)(lr + tid * 4) = make_float4(e0 * inv, e1 * inv, e2 * inv, e3 * inv);

    if (tid == 0) {
        const float lse = m + logf(s);
        const float x = (lse + bptr[0]) * tptr[0];
        out[(size_t)BATCH * QDIM * KDIM + row] = 1.0f / (1.0f + __expf(-x));
    }
}

// ---------------------------------------------------------------------------
extern "C" void kernel_launch(void* const* d_in, const int* in_sizes, int n_in,
                              void* d_out, int out_size) {
    const float* q    = (const float*)d_in[0];
    const float* k    = (const float*)d_in[1];
    const float* temp = (const float*)d_in[2];
    const float* bias = (const float*)d_in[3];
    float* out = (float*)d_out;

    dim3 ggrid(KDIM / TN, QDIM / TM, BATCH);   // (4, 4, 32)
    gemm_bf16split_kernel<<<ggrid, 256>>>(q, k, out);

    softmax_conf_kernel<<<BATCH * QDIM, 128>>>(temp, bias, out);
}